// round 2
// baseline (speedup 1.0000x reference)
#include <cuda_runtime.h>
#include <math.h>
#include <float.h>

#define N_CAND 200000
#define DTXT 768
#define DIMG 1024
#define DC 256
#define KSEL 10

// ---- device scratch (no allocations allowed) ----
__device__ float g_sims[N_CAND];
__device__ int   g_idx[KSEL];
__device__ float g_z[21 * DC];       // pre-LN projections: row0=query, 1..10=neigh_txt, 11..20=neigh_img
__device__ float g_feats[21 * DC];   // post LN+ReLU
__device__ float g_qkv[23 * DC];     // row0=qp, 1..11=kp, 12..22=vp
__device__ float g_out1[DC];
__device__ float g_h1[4 * DC];
__device__ float g_f[DC];

// ============================================================
// 1) cosine-sim scan: one warp per row, float4, grid-stride
// ============================================================
__global__ void sim_kernel(const float* __restrict__ query,
                           const float* __restrict__ cand) {
    __shared__ float4 qs[DTXT / 4];
    for (int i = threadIdx.x; i < DTXT / 4; i += blockDim.x)
        qs[i] = reinterpret_cast<const float4*>(query)[i];
    __syncthreads();

    int lane = threadIdx.x & 31;
    int gw = (blockIdx.x * blockDim.x + threadIdx.x) >> 5;
    int nw = (gridDim.x * blockDim.x) >> 5;

    for (int row = gw; row < N_CAND; row += nw) {
        const float4* rp = reinterpret_cast<const float4*>(cand + (size_t)row * DTXT);
        float dot = 0.f, ss = 0.f;
#pragma unroll
        for (int i = 0; i < 6; i++) {
            float4 c = __ldg(&rp[i * 32 + lane]);
            float4 q = qs[i * 32 + lane];
            dot += c.x * q.x + c.y * q.y + c.z * q.z + c.w * q.w;
            ss  += c.x * c.x + c.y * c.y + c.z * c.z + c.w * c.w;
        }
#pragma unroll
        for (int o = 16; o; o >>= 1) {
            dot += __shfl_xor_sync(0xffffffffu, dot, o);
            ss  += __shfl_xor_sync(0xffffffffu, ss,  o);
        }
        if (lane == 0) {
            float nrm = fmaxf(sqrtf(ss), 1e-12f);
            g_sims[row] = dot / nrm;   // ranking-equivalent to cosine (||q|| const > 0)
        }
    }
}

// ============================================================
// 2) global top-10: per-thread register top-10 + block argmax
// ============================================================
__global__ void topk_kernel() {
    __shared__ float sv[256 * KSEL];
    __shared__ int   si[256 * KSEL];
    __shared__ float rv[256];
    __shared__ int   rj[256];
    int tid = threadIdx.x;

    float tv[KSEL];
    int   ti[KSEL];
#pragma unroll
    for (int j = 0; j < KSEL; j++) { tv[j] = -FLT_MAX; ti[j] = -1; }

    for (int i = tid; i < N_CAND; i += 256) {
        float v = g_sims[i];
        if (v > tv[KSEL - 1]) {
            // insertion position computed BEFORE any writes (pre-insert snapshot)
            int pos = 0;
#pragma unroll
            for (int j = 0; j < KSEL; j++) pos += (tv[j] >= v) ? 1 : 0;
            // shift everything at/below pos down by one
#pragma unroll
            for (int j = KSEL - 2; j >= 0; j--) {
                if (j >= pos) { tv[j + 1] = tv[j]; ti[j + 1] = ti[j]; }
            }
            // insert exactly at pos
#pragma unroll
            for (int j = 0; j < KSEL; j++) {
                if (j == pos) { tv[j] = v; ti[j] = i; }
            }
        }
    }
#pragma unroll
    for (int j = 0; j < KSEL; j++) { sv[tid * KSEL + j] = tv[j]; si[tid * KSEL + j] = ti[j]; }
    __syncthreads();

    for (int s = 0; s < KSEL; s++) {
        float best = -FLT_MAX; int bj = tid * KSEL;
#pragma unroll
        for (int j = 0; j < KSEL; j++) {
            float v = sv[tid * KSEL + j];
            if (v > best) { best = v; bj = tid * KSEL + j; }
        }
        rv[tid] = best; rj[tid] = bj;
        __syncthreads();
        for (int off = 128; off; off >>= 1) {
            if (tid < off && rv[tid + off] > rv[tid]) { rv[tid] = rv[tid + off]; rj[tid] = rj[tid + off]; }
            __syncthreads();
        }
        if (tid == 0) { g_idx[s] = si[rj[0]]; sv[rj[0]] = -FLT_MAX; }
        __syncthreads();
    }
}

// ============================================================
// 3) projection matvecs: warp per output element (21 rows x 256)
// ============================================================
__global__ void proj_kernel(const float* __restrict__ query,
                            const float* __restrict__ cand_text,
                            const float* __restrict__ cand_img,
                            const float* __restrict__ W_txt, const float* __restrict__ b_txt,
                            const float* __restrict__ W_img, const float* __restrict__ b_img) {
    int gw = (blockIdx.x * blockDim.x + threadIdx.x) >> 5;
    int lane = threadIdx.x & 31;
    int r = gw >> 8;
    int c = gw & 255;
    if (r >= 21) return;

    const float* x; const float* W; const float* b; int iters;
    if (r == 0)      { x = query;                                     W = W_txt; b = b_txt; iters = 6; }
    else if (r <= 10){ x = cand_text + (size_t)g_idx[r - 1]  * DTXT;  W = W_txt; b = b_txt; iters = 6; }
    else             { x = cand_img  + (size_t)g_idx[r - 11] * DIMG;  W = W_img; b = b_img; iters = 8; }

    const float4* x4 = reinterpret_cast<const float4*>(x);
    const float4* w4 = reinterpret_cast<const float4*>(W + (size_t)c * (iters * 128));
    float acc = 0.f;
    for (int i = 0; i < iters; i++) {
        float4 a = __ldg(&x4[i * 32 + lane]);
        float4 w = __ldg(&w4[i * 32 + lane]);
        acc += a.x * w.x + a.y * w.y + a.z * w.z + a.w * w.w;
    }
#pragma unroll
    for (int o = 16; o; o >>= 1) acc += __shfl_xor_sync(0xffffffffu, acc, o);
    if (lane == 0) g_z[r * DC + c] = acc + b[c];
}

// ============================================================
// 4) LayerNorm + ReLU per projected row
// ============================================================
__global__ void lnrelu_kernel(const float* __restrict__ gt, const float* __restrict__ bt,
                              const float* __restrict__ gi, const float* __restrict__ bi) {
    __shared__ float red[256];
    int r = blockIdx.x, c = threadIdx.x;
    float v = g_z[r * DC + c];
    red[c] = v; __syncthreads();
    for (int off = 128; off; off >>= 1) { if (c < off) red[c] += red[c + off]; __syncthreads(); }
    float m = red[0] * (1.f / 256.f);
    __syncthreads();
    float d = v - m;
    red[c] = d * d; __syncthreads();
    for (int off = 128; off; off >>= 1) { if (c < off) red[c] += red[c + off]; __syncthreads(); }
    float var = red[0] * (1.f / 256.f);
    const float* gg = (r < 11) ? gt : gi;
    const float* bb = (r < 11) ? bt : bi;
    float y = d * rsqrtf(var + 1e-5f) * gg[c] + bb[c];
    g_feats[r * DC + c] = fmaxf(y, 0.f);
}

// ============================================================
// 5) QKV matvecs: warp per output (23 rows x 256)
// ============================================================
__global__ void qkv_kernel(const float* __restrict__ proto,
                           const float* __restrict__ Wq, const float* __restrict__ bq,
                           const float* __restrict__ Wk, const float* __restrict__ bk,
                           const float* __restrict__ Wv, const float* __restrict__ bv) {
    int gw = (blockIdx.x * blockDim.x + threadIdx.x) >> 5;
    int lane = threadIdx.x & 31;
    int r = gw >> 8;
    int c = gw & 255;
    if (r >= 23) return;

    const float* x; const float* W; const float* b;
    if (r == 0)      { x = g_feats;                                    W = Wq; b = bq; }
    else if (r <= 11){ int n = r - 1;  x = (n == 0) ? proto : (g_feats + n * DC);        W = Wk; b = bk; }
    else             { int n = r - 12; x = (n == 0) ? proto : (g_feats + (10 + n) * DC); W = Wv; b = bv; }

    const float4* x4 = reinterpret_cast<const float4*>(x);
    const float4* w4 = reinterpret_cast<const float4*>(W + (size_t)c * DC);
    float acc = 0.f;
#pragma unroll
    for (int i = 0; i < 2; i++) {
        float4 a = x4[i * 32 + lane];
        float4 w = __ldg(&w4[i * 32 + lane]);
        acc += a.x * w.x + a.y * w.y + a.z * w.z + a.w * w.w;
    }
#pragma unroll
    for (int o = 16; o; o >>= 1) acc += __shfl_xor_sync(0xffffffffu, acc, o);
    if (lane == 0) g_qkv[r * DC + c] = acc + b[c];
}

// ============================================================
// 6) attention (H=4, HD=64, 11 keys) + Wo + residual + LN1
// ============================================================
__global__ void attn_kernel(const float* __restrict__ proto,
                            const float* __restrict__ Wo, const float* __restrict__ bo,
                            const float* __restrict__ g1, const float* __restrict__ be1) {
    __shared__ float qp[DC], kp[11 * DC], vp[11 * DC], at[44], ctx[DC], red[256];
    int t = threadIdx.x;
    qp[t] = g_qkv[t];
    for (int n = 0; n < 11; n++) {
        kp[n * DC + t] = g_qkv[(1 + n) * DC + t];
        vp[n * DC + t] = g_qkv[(12 + n) * DC + t];
    }
    __syncthreads();

    if (t < 44) {
        int h = t / 11, n = t % 11;
        float s = 0.f;
#pragma unroll
        for (int d = 0; d < 64; d++) s += qp[h * 64 + d] * kp[n * DC + h * 64 + d];
        at[t] = s * 0.125f;   // / sqrt(64)
    }
    __syncthreads();
    if (t < 4) {
        float mx = -FLT_MAX;
        for (int n = 0; n < 11; n++) mx = fmaxf(mx, at[t * 11 + n]);
        float sm = 0.f;
        for (int n = 0; n < 11; n++) { float e = expf(at[t * 11 + n] - mx); at[t * 11 + n] = e; sm += e; }
        float inv = 1.f / sm;
        for (int n = 0; n < 11; n++) at[t * 11 + n] *= inv;
    }
    __syncthreads();
    {
        int h = t >> 6, d = t & 63;
        float s = 0.f;
        for (int n = 0; n < 11; n++) s += at[h * 11 + n] * vp[n * DC + h * 64 + d];
        ctx[t] = s;
    }
    __syncthreads();

    float acc = bo[t];
    const float* wr = Wo + (size_t)t * DC;
    for (int d = 0; d < DC; d++) acc += ctx[d] * __ldg(&wr[d]);
    float y = acc + proto[t];

    red[t] = y; __syncthreads();
    for (int off = 128; off; off >>= 1) { if (t < off) red[t] += red[t + off]; __syncthreads(); }
    float m = red[0] * (1.f / 256.f);
    __syncthreads();
    float dd = y - m;
    red[t] = dd * dd; __syncthreads();
    for (int off = 128; off; off >>= 1) { if (t < off) red[t] += red[t + off]; __syncthreads(); }
    float var = red[0] * (1.f / 256.f);
    g_out1[t] = dd * rsqrtf(var + 1e-5f) * g1[t] + be1[t];
}

// ============================================================
// 7) FFN layer 1: warp per output (1024 outputs, dot-256)
// ============================================================
__global__ void ffn1_kernel(const float* __restrict__ W1, const float* __restrict__ b1) {
    int gw = (blockIdx.x * blockDim.x + threadIdx.x) >> 5;
    int lane = threadIdx.x & 31;
    if (gw >= 4 * DC) return;
    const float4* x4 = reinterpret_cast<const float4*>(g_out1);
    const float4* w4 = reinterpret_cast<const float4*>(W1 + (size_t)gw * DC);
    float acc = 0.f;
#pragma unroll
    for (int i = 0; i < 2; i++) {
        float4 a = x4[i * 32 + lane];
        float4 w = __ldg(&w4[i * 32 + lane]);
        acc += a.x * w.x + a.y * w.y + a.z * w.z + a.w * w.w;
    }
#pragma unroll
    for (int o = 16; o; o >>= 1) acc += __shfl_xor_sync(0xffffffffu, acc, o);
    if (lane == 0) g_h1[gw] = fmaxf(acc + b1[gw], 0.f);
}

// ============================================================
// 8) FFN layer 2: warp per output (256 outputs, dot-1024)
// ============================================================
__global__ void ffn2_kernel(const float* __restrict__ W2, const float* __restrict__ b2) {
    int gw = (blockIdx.x * blockDim.x + threadIdx.x) >> 5;
    int lane = threadIdx.x & 31;
    if (gw >= DC) return;
    const float4* x4 = reinterpret_cast<const float4*>(g_h1);
    const float4* w4 = reinterpret_cast<const float4*>(W2 + (size_t)gw * (4 * DC));
    float acc = 0.f;
#pragma unroll
    for (int i = 0; i < 8; i++) {
        float4 a = x4[i * 32 + lane];
        float4 w = __ldg(&w4[i * 32 + lane]);
        acc += a.x * w.x + a.y * w.y + a.z * w.z + a.w * w.w;
    }
#pragma unroll
    for (int o = 16; o; o >>= 1) acc += __shfl_xor_sync(0xffffffffu, acc, o);
    if (lane == 0) g_f[gw] = acc + b2[gw];
}

// ============================================================
// 9) final residual + LN2 + proto add -> d_out
// ============================================================
__global__ void ffn3_kernel(const float* __restrict__ proto,
                            const float* __restrict__ g2, const float* __restrict__ be2,
                            float* __restrict__ out) {
    __shared__ float red[256];
    int t = threadIdx.x;
    float y = g_f[t] + g_out1[t];
    red[t] = y; __syncthreads();
    for (int off = 128; off; off >>= 1) { if (t < off) red[t] += red[t + off]; __syncthreads(); }
    float m = red[0] * (1.f / 256.f);
    __syncthreads();
    float dd = y - m;
    red[t] = dd * dd; __syncthreads();
    for (int off = 128; off; off >>= 1) { if (t < off) red[t] += red[t + off]; __syncthreads(); }
    float var = red[0] * (1.f / 256.f);
    out[t] = dd * rsqrtf(var + 1e-5f) * g2[t] + be2[t] + proto[t];
}

// ============================================================
extern "C" void kernel_launch(void* const* d_in, const int* in_sizes, int n_in,
                              void* d_out, int out_size) {
    const float* query     = (const float*)d_in[0];
    const float* cand_text = (const float*)d_in[1];
    const float* cand_img  = (const float*)d_in[2];
    const float* proto     = (const float*)d_in[3];
    const float* W_txt  = (const float*)d_in[4];
    const float* b_txt  = (const float*)d_in[5];
    const float* g_txt  = (const float*)d_in[6];
    const float* be_txt = (const float*)d_in[7];
    const float* W_img  = (const float*)d_in[8];
    const float* b_img  = (const float*)d_in[9];
    const float* g_img  = (const float*)d_in[10];
    const float* be_img = (const float*)d_in[11];
    const float* Wq = (const float*)d_in[12];
    const float* bq = (const float*)d_in[13];
    const float* Wk = (const float*)d_in[14];
    const float* bk = (const float*)d_in[15];
    const float* Wv = (const float*)d_in[16];
    const float* bv = (const float*)d_in[17];
    const float* Wo = (const float*)d_in[18];
    const float* bo = (const float*)d_in[19];
    const float* g1  = (const float*)d_in[20];
    const float* be1 = (const float*)d_in[21];
    const float* W1 = (const float*)d_in[22];
    const float* b1 = (const float*)d_in[23];
    const float* W2 = (const float*)d_in[24];
    const float* b2 = (const float*)d_in[25];
    const float* g2  = (const float*)d_in[26];
    const float* be2 = (const float*)d_in[27];
    float* out = (float*)d_out;

    sim_kernel<<<1184, 256>>>(query, cand_text);
    topk_kernel<<<1, 256>>>();
    proj_kernel<<<672, 256>>>(query, cand_text, cand_img, W_txt, b_txt, W_img, b_img);
    lnrelu_kernel<<<21, 256>>>(g_txt, be_txt, g_img, be_img);
    qkv_kernel<<<736, 256>>>(proto, Wq, bq, Wk, bk, Wv, bv);
    attn_kernel<<<1, 256>>>(proto, Wo, bo, g1, be1);
    ffn1_kernel<<<128, 256>>>(W1, b1);
    ffn2_kernel<<<32, 256>>>(W2, b2);
    ffn3_kernel<<<1, 256>>>(proto, g2, be2, out);
}

// round 3
// speedup vs baseline: 3.7954x; 3.7954x over previous
#include <cuda_runtime.h>
#include <math.h>
#include <float.h>

#define N_CAND 200000
#define DTXT 768
#define DIMG 1024
#define DC 256
#define KSEL 10
#define TKA_BLOCKS 200
#define TKA_CHUNK 1000

// ---- device scratch (no allocations allowed) ----
__device__ float g_sims[N_CAND];
__device__ float g_cv[TKA_BLOCKS * KSEL];
__device__ int   g_ci[TKA_BLOCKS * KSEL];
__device__ int   g_idx[KSEL];
__device__ float g_z[21 * DC];       // pre-LN projections
__device__ float g_feats[21 * DC];   // post LN+ReLU
__device__ float g_qkv[23 * DC];     // row0=qp, 1..11=kp, 12..22=vp
__device__ float g_out1[DC];
__device__ float g_h1[4 * DC];
__device__ float g_f[DC];

// ============================================================
// 1) cosine-sim scan: warp per row-pair, float4, oe=2 CTAs/SM
// ============================================================
__global__ void __launch_bounds__(1024, 2) sim_kernel(const float* __restrict__ query,
                                                      const float* __restrict__ cand) {
    __shared__ float4 qs[DTXT / 4];
    for (int i = threadIdx.x; i < DTXT / 4; i += blockDim.x)
        qs[i] = reinterpret_cast<const float4*>(query)[i];
    __syncthreads();

    int lane = threadIdx.x & 31;
    int gw = (blockIdx.x * blockDim.x + threadIdx.x) >> 5;
    int nw = (gridDim.x * blockDim.x) >> 5;   // 9472 warps

    for (int row = gw * 2; row < N_CAND; row += 2 * nw) {
        const float4* r0 = reinterpret_cast<const float4*>(cand + (size_t)row * DTXT);
        const float4* r1 = reinterpret_cast<const float4*>(cand + (size_t)(row + 1) * DTXT);
        float4 c0[6], c1[6];
#pragma unroll
        for (int i = 0; i < 6; i++) c0[i] = __ldg(&r0[i * 32 + lane]);
#pragma unroll
        for (int i = 0; i < 6; i++) c1[i] = __ldg(&r1[i * 32 + lane]);

        float d0 = 0.f, s0 = 0.f, d1 = 0.f, s1 = 0.f;
#pragma unroll
        for (int i = 0; i < 6; i++) {
            float4 q = qs[i * 32 + lane];
            d0 += c0[i].x * q.x + c0[i].y * q.y + c0[i].z * q.z + c0[i].w * q.w;
            s0 += c0[i].x * c0[i].x + c0[i].y * c0[i].y + c0[i].z * c0[i].z + c0[i].w * c0[i].w;
            d1 += c1[i].x * q.x + c1[i].y * q.y + c1[i].z * q.z + c1[i].w * q.w;
            s1 += c1[i].x * c1[i].x + c1[i].y * c1[i].y + c1[i].z * c1[i].z + c1[i].w * c1[i].w;
        }
#pragma unroll
        for (int o = 16; o; o >>= 1) {
            d0 += __shfl_xor_sync(0xffffffffu, d0, o);
            s0 += __shfl_xor_sync(0xffffffffu, s0, o);
            d1 += __shfl_xor_sync(0xffffffffu, d1, o);
            s1 += __shfl_xor_sync(0xffffffffu, s1, o);
        }
        if (lane == 0) {
            g_sims[row]     = d0 / fmaxf(sqrtf(s0), 1e-12f);
            g_sims[row + 1] = d1 / fmaxf(sqrtf(s1), 1e-12f);
        }
    }
}

// ---- shared top-k helpers (per-thread register top-10 insert) ----
__device__ __forceinline__ void tk_insert(float v, int i, float* tv, int* ti) {
    if (v > tv[KSEL - 1]) {
        int pos = 0;
#pragma unroll
        for (int j = 0; j < KSEL; j++) pos += (tv[j] >= v) ? 1 : 0;
#pragma unroll
        for (int j = KSEL - 2; j >= 0; j--) {
            if (j >= pos) { tv[j + 1] = tv[j]; ti[j + 1] = ti[j]; }
        }
#pragma unroll
        for (int j = 0; j < KSEL; j++) {
            if (j == pos) { tv[j] = v; ti[j] = i; }
        }
    }
}

// 10-round block argmax over 256 threads x KSEL shared candidates
__device__ __forceinline__ void tk_select(float* sv, int* si, float* ov, int* oi) {
    __shared__ float rv[256];
    __shared__ int   rj[256];
    int tid = threadIdx.x;
    for (int s = 0; s < KSEL; s++) {
        float best = -FLT_MAX; int bj = tid * KSEL;
#pragma unroll
        for (int j = 0; j < KSEL; j++) {
            float v = sv[tid * KSEL + j];
            if (v > best) { best = v; bj = tid * KSEL + j; }
        }
        rv[tid] = best; rj[tid] = bj;
        __syncthreads();
        for (int off = 128; off; off >>= 1) {
            if (tid < off && rv[tid + off] > rv[tid]) { rv[tid] = rv[tid + off]; rj[tid] = rj[tid + off]; }
            __syncthreads();
        }
        if (tid == 0) { ov[s] = sv[rj[0]]; oi[s] = si[rj[0]]; sv[rj[0]] = -FLT_MAX; }
        __syncthreads();
    }
}

// ============================================================
// 2a) top-10 phase A: per-block top-10 over a 1000-row chunk
// ============================================================
__global__ void topkA_kernel() {
    __shared__ float sv[256 * KSEL];
    __shared__ int   si[256 * KSEL];
    int tid = threadIdx.x;
    int base = blockIdx.x * TKA_CHUNK;

    float tv[KSEL]; int ti[KSEL];
#pragma unroll
    for (int j = 0; j < KSEL; j++) { tv[j] = -FLT_MAX; ti[j] = -1; }
    for (int i = tid; i < TKA_CHUNK; i += 256)
        tk_insert(g_sims[base + i], base + i, tv, ti);
#pragma unroll
    for (int j = 0; j < KSEL; j++) { sv[tid * KSEL + j] = tv[j]; si[tid * KSEL + j] = ti[j]; }
    __syncthreads();
    tk_select(sv, si, &g_cv[blockIdx.x * KSEL], &g_ci[blockIdx.x * KSEL]);
}

// ============================================================
// 2b) top-10 phase B: reduce 2000 candidates to final 10
// ============================================================
__global__ void topkB_kernel() {
    __shared__ float sv[256 * KSEL];
    __shared__ int   si[256 * KSEL];
    __shared__ float ov[KSEL];
    int tid = threadIdx.x;

    float tv[KSEL]; int ti[KSEL];
#pragma unroll
    for (int j = 0; j < KSEL; j++) { tv[j] = -FLT_MAX; ti[j] = -1; }
    for (int i = tid; i < TKA_BLOCKS * KSEL; i += 256)
        tk_insert(g_cv[i], g_ci[i], tv, ti);
#pragma unroll
    for (int j = 0; j < KSEL; j++) { sv[tid * KSEL + j] = tv[j]; si[tid * KSEL + j] = ti[j]; }
    __syncthreads();
    tk_select(sv, si, ov, g_idx);
}

// ============================================================
// 3) projection matvecs: warp per output element (21 rows x 256)
// ============================================================
__global__ void proj_kernel(const float* __restrict__ query,
                            const float* __restrict__ cand_text,
                            const float* __restrict__ cand_img,
                            const float* __restrict__ W_txt, const float* __restrict__ b_txt,
                            const float* __restrict__ W_img, const float* __restrict__ b_img) {
    int gw = (blockIdx.x * blockDim.x + threadIdx.x) >> 5;
    int lane = threadIdx.x & 31;
    int r = gw >> 8;
    int c = gw & 255;
    if (r >= 21) return;

    const float* x; const float* W; const float* b; int iters;
    if (r == 0)      { x = query;                                     W = W_txt; b = b_txt; iters = 6; }
    else if (r <= 10){ x = cand_text + (size_t)g_idx[r - 1]  * DTXT;  W = W_txt; b = b_txt; iters = 6; }
    else             { x = cand_img  + (size_t)g_idx[r - 11] * DIMG;  W = W_img; b = b_img; iters = 8; }

    const float4* x4 = reinterpret_cast<const float4*>(x);
    const float4* w4 = reinterpret_cast<const float4*>(W + (size_t)c * (iters * 128));
    float acc = 0.f;
    for (int i = 0; i < iters; i++) {
        float4 a = __ldg(&x4[i * 32 + lane]);
        float4 w = __ldg(&w4[i * 32 + lane]);
        acc += a.x * w.x + a.y * w.y + a.z * w.z + a.w * w.w;
    }
#pragma unroll
    for (int o = 16; o; o >>= 1) acc += __shfl_xor_sync(0xffffffffu, acc, o);
    if (lane == 0) g_z[r * DC + c] = acc + b[c];
}

// ============================================================
// 4) LayerNorm + ReLU per projected row
// ============================================================
__global__ void lnrelu_kernel(const float* __restrict__ gt, const float* __restrict__ bt,
                              const float* __restrict__ gi, const float* __restrict__ bi) {
    __shared__ float red[256];
    int r = blockIdx.x, c = threadIdx.x;
    float v = g_z[r * DC + c];
    red[c] = v; __syncthreads();
    for (int off = 128; off; off >>= 1) { if (c < off) red[c] += red[c + off]; __syncthreads(); }
    float m = red[0] * (1.f / 256.f);
    __syncthreads();
    float d = v - m;
    red[c] = d * d; __syncthreads();
    for (int off = 128; off; off >>= 1) { if (c < off) red[c] += red[c + off]; __syncthreads(); }
    float var = red[0] * (1.f / 256.f);
    const float* gg = (r < 11) ? gt : gi;
    const float* bb = (r < 11) ? bt : bi;
    float y = d * rsqrtf(var + 1e-5f) * gg[c] + bb[c];
    g_feats[r * DC + c] = fmaxf(y, 0.f);
}

// ============================================================
// 5) QKV matvecs: warp per output (23 rows x 256)
// ============================================================
__global__ void qkv_kernel(const float* __restrict__ proto,
                           const float* __restrict__ Wq, const float* __restrict__ bq,
                           const float* __restrict__ Wk, const float* __restrict__ bk,
                           const float* __restrict__ Wv, const float* __restrict__ bv) {
    int gw = (blockIdx.x * blockDim.x + threadIdx.x) >> 5;
    int lane = threadIdx.x & 31;
    int r = gw >> 8;
    int c = gw & 255;
    if (r >= 23) return;

    const float* x; const float* W; const float* b;
    if (r == 0)      { x = g_feats;                                    W = Wq; b = bq; }
    else if (r <= 11){ int n = r - 1;  x = (n == 0) ? proto : (g_feats + n * DC);        W = Wk; b = bk; }
    else             { int n = r - 12; x = (n == 0) ? proto : (g_feats + (10 + n) * DC); W = Wv; b = bv; }

    const float4* x4 = reinterpret_cast<const float4*>(x);
    const float4* w4 = reinterpret_cast<const float4*>(W + (size_t)c * DC);
    float acc = 0.f;
#pragma unroll
    for (int i = 0; i < 2; i++) {
        float4 a = x4[i * 32 + lane];
        float4 w = __ldg(&w4[i * 32 + lane]);
        acc += a.x * w.x + a.y * w.y + a.z * w.z + a.w * w.w;
    }
#pragma unroll
    for (int o = 16; o; o >>= 1) acc += __shfl_xor_sync(0xffffffffu, acc, o);
    if (lane == 0) g_qkv[r * DC + c] = acc + b[c];
}

// ============================================================
// 6) attention + Wo (coalesced warp-per-output) + residual + LN1
// ============================================================
__global__ void __launch_bounds__(1024, 1) attn_kernel(const float* __restrict__ proto,
                            const float* __restrict__ Wo, const float* __restrict__ bo,
                            const float* __restrict__ g1, const float* __restrict__ be1) {
    __shared__ float qp[DC], kp[11 * DC], vp[11 * DC], at[44], ctx[DC], sy[DC], red[256];
    int t = threadIdx.x;
    int lane = t & 31, w = t >> 5;

    for (int i = t; i < DC; i += 1024) qp[i] = g_qkv[i];
    for (int i = t; i < 11 * DC; i += 1024) {
        kp[i] = g_qkv[DC + i];
        vp[i] = g_qkv[12 * DC + i];
    }
    __syncthreads();

    if (t < 44) {
        int h = t / 11, n = t % 11;
        float s = 0.f;
#pragma unroll
        for (int d = 0; d < 64; d++) s += qp[h * 64 + d] * kp[n * DC + h * 64 + d];
        at[t] = s * 0.125f;
    }
    __syncthreads();
    if (t < 4) {
        float mx = -FLT_MAX;
        for (int n = 0; n < 11; n++) mx = fmaxf(mx, at[t * 11 + n]);
        float sm = 0.f;
        for (int n = 0; n < 11; n++) { float e = expf(at[t * 11 + n] - mx); at[t * 11 + n] = e; sm += e; }
        float inv = 1.f / sm;
        for (int n = 0; n < 11; n++) at[t * 11 + n] *= inv;
    }
    __syncthreads();
    if (t < DC) {
        int h = t >> 6;
        float s = 0.f;
        for (int n = 0; n < 11; n++) s += at[h * 11 + n] * vp[n * DC + t];
        ctx[t] = s;
    }
    __syncthreads();

    // Wo matvec: 32 warps x 8 outputs, coalesced float4 lanes
    const float4* c4 = reinterpret_cast<const float4*>(ctx);
#pragma unroll
    for (int j = 0; j < 8; j++) {
        int c = w * 8 + j;
        const float4* w4 = reinterpret_cast<const float4*>(Wo + (size_t)c * DC);
        float acc = 0.f;
#pragma unroll
        for (int i = 0; i < 2; i++) {
            float4 a = c4[i * 32 + lane];
            float4 ww = __ldg(&w4[i * 32 + lane]);
            acc += a.x * ww.x + a.y * ww.y + a.z * ww.z + a.w * ww.w;
        }
#pragma unroll
        for (int o = 16; o; o >>= 1) acc += __shfl_xor_sync(0xffffffffu, acc, o);
        if (lane == 0) sy[c] = acc + bo[c] + proto[c];
    }
    __syncthreads();

    // LN1 over sy[256]
    if (t < 256) red[t] = sy[t];
    __syncthreads();
    for (int off = 128; off; off >>= 1) { if (t < off) red[t] += red[t + off]; __syncthreads(); }
    float m = red[0] * (1.f / 256.f);
    __syncthreads();
    if (t < 256) { float dd = sy[t] - m; red[t] = dd * dd; }
    __syncthreads();
    for (int off = 128; off; off >>= 1) { if (t < off) red[t] += red[t + off]; __syncthreads(); }
    float var = red[0] * (1.f / 256.f);
    if (t < 256) g_out1[t] = (sy[t] - m) * rsqrtf(var + 1e-5f) * g1[t] + be1[t];
}

// ============================================================
// 7) FFN layer 1: warp per output (1024 outputs, dot-256)
// ============================================================
__global__ void ffn1_kernel(const float* __restrict__ W1, const float* __restrict__ b1) {
    int gw = (blockIdx.x * blockDim.x + threadIdx.x) >> 5;
    int lane = threadIdx.x & 31;
    if (gw >= 4 * DC) return;
    const float4* x4 = reinterpret_cast<const float4*>(g_out1);
    const float4* w4 = reinterpret_cast<const float4*>(W1 + (size_t)gw * DC);
    float acc = 0.f;
#pragma unroll
    for (int i = 0; i < 2; i++) {
        float4 a = x4[i * 32 + lane];
        float4 w = __ldg(&w4[i * 32 + lane]);
        acc += a.x * w.x + a.y * w.y + a.z * w.z + a.w * w.w;
    }
#pragma unroll
    for (int o = 16; o; o >>= 1) acc += __shfl_xor_sync(0xffffffffu, acc, o);
    if (lane == 0) g_h1[gw] = fmaxf(acc + b1[gw], 0.f);
}

// ============================================================
// 8) FFN layer 2: warp per output (256 outputs, dot-1024)
// ============================================================
__global__ void ffn2_kernel(const float* __restrict__ W2, const float* __restrict__ b2) {
    int gw = (blockIdx.x * blockDim.x + threadIdx.x) >> 5;
    int lane = threadIdx.x & 31;
    if (gw >= DC) return;
    const float4* x4 = reinterpret_cast<const float4*>(g_h1);
    const float4* w4 = reinterpret_cast<const float4*>(W2 + (size_t)gw * (4 * DC));
    float acc = 0.f;
#pragma unroll
    for (int i = 0; i < 8; i++) {
        float4 a = x4[i * 32 + lane];
        float4 w = __ldg(&w4[i * 32 + lane]);
        acc += a.x * w.x + a.y * w.y + a.z * w.z + a.w * w.w;
    }
#pragma unroll
    for (int o = 16; o; o >>= 1) acc += __shfl_xor_sync(0xffffffffu, acc, o);
    if (lane == 0) g_f[gw] = acc + b2[gw];
}

// ============================================================
// 9) final residual + LN2 + proto add -> d_out
// ============================================================
__global__ void ffn3_kernel(const float* __restrict__ proto,
                            const float* __restrict__ g2, const float* __restrict__ be2,
                            float* __restrict__ out) {
    __shared__ float red[256];
    int t = threadIdx.x;
    float y = g_f[t] + g_out1[t];
    red[t] = y; __syncthreads();
    for (int off = 128; off; off >>= 1) { if (t < off) red[t] += red[t + off]; __syncthreads(); }
    float m = red[0] * (1.f / 256.f);
    __syncthreads();
    float dd = y - m;
    red[t] = dd * dd; __syncthreads();
    for (int off = 128; off; off >>= 1) { if (t < off) red[t] += red[t + off]; __syncthreads(); }
    float var = red[0] * (1.f / 256.f);
    out[t] = dd * rsqrtf(var + 1e-5f) * g2[t] + be2[t] + proto[t];
}

// ============================================================
extern "C" void kernel_launch(void* const* d_in, const int* in_sizes, int n_in,
                              void* d_out, int out_size) {
    const float* query     = (const float*)d_in[0];
    const float* cand_text = (const float*)d_in[1];
    const float* cand_img  = (const float*)d_in[2];
    const float* proto     = (const float*)d_in[3];
    const float* W_txt  = (const float*)d_in[4];
    const float* b_txt  = (const float*)d_in[5];
    const float* g_txt  = (const float*)d_in[6];
    const float* be_txt = (const float*)d_in[7];
    const float* W_img  = (const float*)d_in[8];
    const float* b_img  = (const float*)d_in[9];
    const float* g_img  = (const float*)d_in[10];
    const float* be_img = (const float*)d_in[11];
    const float* Wq = (const float*)d_in[12];
    const float* bq = (const float*)d_in[13];
    const float* Wk = (const float*)d_in[14];
    const float* bk = (const float*)d_in[15];
    const float* Wv = (const float*)d_in[16];
    const float* bv = (const float*)d_in[17];
    const float* Wo = (const float*)d_in[18];
    const float* bo = (const float*)d_in[19];
    const float* g1  = (const float*)d_in[20];
    const float* be1 = (const float*)d_in[21];
    const float* W1 = (const float*)d_in[22];
    const float* b1 = (const float*)d_in[23];
    const float* W2 = (const float*)d_in[24];
    const float* b2 = (const float*)d_in[25];
    const float* g2  = (const float*)d_in[26];
    const float* be2 = (const float*)d_in[27];
    float* out = (float*)d_out;

    sim_kernel<<<296, 1024>>>(query, cand_text);
    topkA_kernel<<<TKA_BLOCKS, 256>>>();
    topkB_kernel<<<1, 256>>>();
    proj_kernel<<<672, 256>>>(query, cand_text, cand_img, W_txt, b_txt, W_img, b_img);
    lnrelu_kernel<<<21, 256>>>(g_txt, be_txt, g_img, be_img);
    qkv_kernel<<<736, 256>>>(proto, Wq, bq, Wk, bk, Wv, bv);
    attn_kernel<<<1, 1024>>>(proto, Wo, bo, g1, be1);
    ffn1_kernel<<<128, 256>>>(W1, b1);
    ffn2_kernel<<<32, 256>>>(W2, b2);
    ffn3_kernel<<<1, 256>>>(proto, g2, be2, out);
}